// round 12
// baseline (speedup 1.0000x reference)
#include <cuda_runtime.h>
#include <cstdint>
#include <cstddef>

#define BATCH  8
#define HIDC   128
#define HROWS  64
#define WCOLS  64
#define TSTEPS 127   // 2*W - 1

typedef unsigned long long ull;

// ---------------- scratch (static device globals; no runtime allocation) ----
__device__ float g_Z[(size_t)BATCH * HROWS * WCOLS * 512]; // [b][r][w][o], includes b_is
__device__ float g_h[2 * BATCH * (HROWS + 1) * HIDC];      // [parity][b][row+1][c]; slot 0 = zero pad
__device__ int   g_done[BATCH];                            // per-batch step counters (16 CTAs each)

// ---------------- packed f32x2 helpers -------------------------------------
__device__ __forceinline__ ull fma2(ull a, ull b, ull c) {
    ull d;
    asm("fma.rn.f32x2 %0, %1, %2, %3;" : "=l"(d) : "l"(a), "l"(b), "l"(c));
    return d;
}
__device__ __forceinline__ ull dup2(float x) {
    ull d;
    asm("mov.b64 %0, {%1, %1};" : "=l"(d) : "f"(x));
    return d;
}
__device__ __forceinline__ float sigmoidf_fast(float z) {
    return __fdividef(1.0f, 1.0f + __expf(-z));
}
__device__ __forceinline__ float tanhf_fast(float z) {
    // tanh(x) = 1 - 2/(exp(2x)+1); saturates correctly at +/-inf
    return 1.0f - __fdividef(2.0f, __expf(2.0f * z) + 1.0f);
}

// ============================================================================
// Kernel 0: zero h state + flags (re-run on every graph replay)
// ============================================================================
__global__ void init_kernel() {
    int i = blockIdx.x * blockDim.x + threadIdx.x;
    const int n = 2 * BATCH * (HROWS + 1) * HIDC;
    if (i < n) g_h[i] = 0.0f;
    if (i < BATCH) g_done[i] = 0;
}

// ============================================================================
// Kernel 1: Z[b][r][w][o] = b_is[o] + sum_c x[b][c][r][w] * w_is[o][c]
// grid = (512 = b*64+r, 4 out-tiles of 128), 256 threads
// ============================================================================
#define ZPREP_SMEM ((8192 + 128 * 132) * 4)

__global__ void __launch_bounds__(256) zprep_kernel(
    const float* __restrict__ x, const float* __restrict__ w_is,
    const float* __restrict__ b_is)
{
    extern __shared__ float sm1[];
    float* xsh = sm1;          // [k=128][w=64]
    float* wsh = sm1 + 8192;   // [k=128][ol=128 pad 132]

    const int tid = threadIdx.x;
    const int b   = blockIdx.x >> 6;
    const int r   = blockIdx.x & 63;
    const int nt  = blockIdx.y;

#pragma unroll 8
    for (int i = 0; i < 32; ++i) {
        int idx = tid + (i << 8);
        int c = idx >> 6, w = idx & 63;
        xsh[idx] = x[(((size_t)(b << 7) + c) << 12) + (r << 6) + w];
    }
#pragma unroll 8
    for (int i = 0; i < 64; ++i) {
        int idx = tid + (i << 8);
        int ol = idx >> 7, c = idx & 127;
        wsh[c * 132 + ol] = w_is[(((nt << 7) + ol) << 7) + c];
    }
    __syncthreads();

    const int pc = (tid & 15) << 2;  // 4 w-positions
    const int oc = (tid >> 4) << 3;  // 8 outputs
    ull acc[16];
#pragma unroll
    for (int i = 0; i < 16; ++i) acc[i] = 0ull;

#pragma unroll 4
    for (int k = 0; k < 128; ++k) {
        float4 xv = *(const float4*)(xsh + (k << 6) + pc);
        ulonglong2 w0 = *(const ulonglong2*)(wsh + k * 132 + oc);
        ulonglong2 w1 = *(const ulonglong2*)(wsh + k * 132 + oc + 4);
        ull x0 = dup2(xv.x), x1 = dup2(xv.y), x2 = dup2(xv.z), x3 = dup2(xv.w);
        acc[ 0] = fma2(x0, w0.x, acc[ 0]);  acc[ 1] = fma2(x0, w0.y, acc[ 1]);
        acc[ 2] = fma2(x0, w1.x, acc[ 2]);  acc[ 3] = fma2(x0, w1.y, acc[ 3]);
        acc[ 4] = fma2(x1, w0.x, acc[ 4]);  acc[ 5] = fma2(x1, w0.y, acc[ 5]);
        acc[ 6] = fma2(x1, w1.x, acc[ 6]);  acc[ 7] = fma2(x1, w1.y, acc[ 7]);
        acc[ 8] = fma2(x2, w0.x, acc[ 8]);  acc[ 9] = fma2(x2, w0.y, acc[ 9]);
        acc[10] = fma2(x2, w1.x, acc[10]);  acc[11] = fma2(x2, w1.y, acc[11]);
        acc[12] = fma2(x3, w0.x, acc[12]);  acc[13] = fma2(x3, w0.y, acc[13]);
        acc[14] = fma2(x3, w1.x, acc[14]);  acc[15] = fma2(x3, w1.y, acc[15]);
    }

    float bo[8];
#pragma unroll
    for (int j = 0; j < 8; ++j) bo[j] = b_is[(nt << 7) + oc + j];

#pragma unroll
    for (int p = 0; p < 4; ++p) {
        float2 a0 = *(float2*)&acc[p * 4 + 0];
        float2 a1 = *(float2*)&acc[p * 4 + 1];
        float2 a2 = *(float2*)&acc[p * 4 + 2];
        float2 a3 = *(float2*)&acc[p * 4 + 3];
        float* zp = g_Z + (((size_t)blockIdx.x << 6) + pc + p) * 512 + (nt << 7) + oc;
        *(float4*)(zp)     = make_float4(a0.x + bo[0], a0.y + bo[1], a1.x + bo[2], a1.y + bo[3]);
        *(float4*)(zp + 4) = make_float4(a2.x + bo[4], a2.y + bo[5], a3.x + bo[6], a3.y + bo[7]);
    }
}

// ============================================================================
// Kernel 2: persistent diagonal scan.
// grid = 128 CTAs: bx = b*16 + rg*4 + cg. CTA owns rows [rg*16, rg*16+16),
// hidden channels [cg*32, cg*32+32) -> gate outputs {g*128 + cg*32 + j}.
// 128 threads. Recurrence weights resident in shared for all 127 steps.
// ============================================================================
#define SCAN_SMEM ((32768 + 9216 + 16 * 132) * 4)   // 176384 bytes

__global__ void __launch_bounds__(128, 1) scan_kernel(
    const float* __restrict__ w_ss, const float* __restrict__ b_is,
    const float* __restrict__ b_ss, float* __restrict__ out)
{
    extern __shared__ float sm[];
    float*  Wsh = sm;                        // [k=256][ol=128]
    float2* hsh = (float2*)(sm + 32768);     // [k=256][m=16 pad 18], (h,h) duplicated
    float*  zsh = sm + 32768 + 9216;         // [m=16][ol=128 pad 132]

    const int tid = threadIdx.x;
    const int bx  = blockIdx.x;
    const int cg  = bx & 3;
    const int rg  = (bx >> 2) & 3;
    const int b   = bx >> 4;
    const int r0  = rg << 4;
    const int cbase = cg << 5;

    // resident weights: k<128 -> (dk=0, c=k) pairs h[r-1]; k>=128 -> (dk=1, c=k-128) pairs h[r]
#pragma unroll 8
    for (int i = 0; i < 256; ++i) {
        int idx = tid + (i << 7);
        int k = idx >> 7, ol = idx & 127;
        int g = ol >> 5, j = ol & 31;
        int oglb = (g << 7) + cbase + j;
        int dk = k >> 7, c = k & 127;
        Wsh[idx] = w_ss[(oglb << 8) + (c << 1) + dk];
    }

    // update-phase mapping: row mu (16), 4 channels jq..jq+3 within cg
    const int mu = tid >> 3;
    const int jq = (tid & 7) << 2;
    const int ru = r0 + mu;

    float bisr[16], bssr[16];
#pragma unroll
    for (int g = 0; g < 4; ++g)
#pragma unroll
        for (int q = 0; q < 4; ++q) {
            int o = (g << 7) + cbase + jq + q;
            bisr[g * 4 + q] = b_is[o];
            bssr[g * 4 + q] = b_ss[o];
        }
    float creg[4] = {0.f, 0.f, 0.f, 0.f};

    // GEMM mapping: warp tr handles rows tr*4..tr*4+3; lane tc handles outputs tc*4..tc*4+3
    const int tc = tid & 31;
    const int tr = tid >> 5;
    const float*  wbase = Wsh + (tc << 2);
    const float2* hbase = hsh + (tr << 2);

    const size_t hb_b = (size_t)b * (HROWS + 1) * HIDC;
    int* dflag = &g_done[b];

    __syncthreads();

    for (int t = 0; t < TSTEPS; ++t) {
        if (t > 0) {
            if (tid == 0) {
                const int need = 16 * t;
                while (*(volatile int*)dflag < need) {}
            }
            __syncthreads();
        }
        const float* hin  = g_h + (size_t)(t & 1) * (BATCH * (HROWS + 1) * HIDC) + hb_b;
        float*       hout = g_h + (size_t)((t + 1) & 1) * (BATCH * (HROWS + 1) * HIDC) + hb_b;

        // build duplicated h tile (tid = channel; slot s holds global row s-1)
        {
            float hv[17];
#pragma unroll
            for (int rr = 0; rr < 17; ++rr)
                hv[rr] = hin[(r0 + rr) * HIDC + tid];
#pragma unroll
            for (int m = 0; m < 16; ++m) {
                hsh[tid * 18 + m]         = make_float2(hv[m],     hv[m]);     // h[r-1]
                hsh[(tid + 128) * 18 + m] = make_float2(hv[m + 1], hv[m + 1]); // h[r]
            }
        }
        __syncthreads();

        // micro-GEMM: hs[m][ol] = sum_k Wsh[k][ol] * h_k[m]
        ull acc[8];
#pragma unroll
        for (int i = 0; i < 8; ++i) acc[i] = 0ull;
#pragma unroll 4
        for (int k = 0; k < 256; ++k) {
            ulonglong2 w2  = *(const ulonglong2*)(wbase + (k << 7));
            ulonglong2 h01 = *(const ulonglong2*)(hbase + k * 18);
            ulonglong2 h23 = *(const ulonglong2*)(hbase + k * 18 + 2);
            acc[0] = fma2(h01.x, w2.x, acc[0]);  acc[1] = fma2(h01.x, w2.y, acc[1]);
            acc[2] = fma2(h01.y, w2.x, acc[2]);  acc[3] = fma2(h01.y, w2.y, acc[3]);
            acc[4] = fma2(h23.x, w2.x, acc[4]);  acc[5] = fma2(h23.x, w2.y, acc[5]);
            acc[6] = fma2(h23.y, w2.x, acc[6]);  acc[7] = fma2(h23.y, w2.y, acc[7]);
        }
#pragma unroll
        for (int ri = 0; ri < 4; ++ri) {
            float2 p0 = *(float2*)&acc[ri * 2 + 0];
            float2 p1 = *(float2*)&acc[ri * 2 + 1];
            *(float4*)(zsh + ((tr << 2) + ri) * 132 + (tc << 2)) =
                make_float4(p0.x, p0.y, p1.x, p1.y);
        }
        __syncthreads();

        // gates + state update (thread: row ru, channels cbase+jq .. +3)
        const int w = t - ru;
        const bool inband = (w >= 0) && (w < WCOLS);
        float zs[16];
        if (inband) {
            const float* Zp = g_Z + ((((size_t)b * HROWS + ru) * WCOLS + w) << 9) + cbase + jq;
#pragma unroll
            for (int g = 0; g < 4; ++g) {
                float4 zv = *(const float4*)(Zp + (g << 7));
                zs[g * 4 + 0] = zv.x; zs[g * 4 + 1] = zv.y;
                zs[g * 4 + 2] = zv.z; zs[g * 4 + 3] = zv.w;
            }
        } else {
#pragma unroll
            for (int i = 0; i < 16; ++i) zs[i] = bisr[i];
        }
        float4 zr0 = *(const float4*)(zsh + mu * 132 +  0 + jq);
        float4 zr1 = *(const float4*)(zsh + mu * 132 + 32 + jq);
        float4 zr2 = *(const float4*)(zsh + mu * 132 + 64 + jq);
        float4 zr3 = *(const float4*)(zsh + mu * 132 + 96 + jq);
        float hs0[4] = {zr0.x, zr0.y, zr0.z, zr0.w};
        float hs1[4] = {zr1.x, zr1.y, zr1.z, zr1.w};
        float hs2[4] = {zr2.x, zr2.y, zr2.z, zr2.w};
        float hs3[4] = {zr3.x, zr3.y, zr3.z, zr3.w};

        float hvals[4];
#pragma unroll
        for (int q = 0; q < 4; ++q) {
            float zi = hs0[q] + zs[0  + q] + bssr[0  + q];
            float zf = hs1[q] + zs[4  + q] + bssr[4  + q];
            float zo = hs2[q] + zs[8  + q] + bssr[8  + q];
            float zg = hs3[q] + zs[12 + q] + bssr[12 + q];
            float ig = sigmoidf_fast(zi);
            float fg = sigmoidf_fast(zf);
            float og = sigmoidf_fast(zo);
            float gg = tanhf_fast(zg);
            float cc = fg * creg[q] + ig * gg;
            creg[q] = cc;
            hvals[q] = og * tanhf_fast(cc);
        }
        // publish h (slot ru+1), write output if in-band
        *(float4*)(hout + (ru + 1) * HIDC + cbase + jq) =
            make_float4(hvals[0], hvals[1], hvals[2], hvals[3]);
        if (inband) {
#pragma unroll
            for (int q = 0; q < 4; ++q) {
                int c = cbase + jq + q;
                out[((((size_t)b << 7) + c) << 12) + (ru << 6) + w] = hvals[q];
            }
        }

        __threadfence();      // release: publish hout before flag
        __syncthreads();
        if (tid == 0) atomicAdd(dflag, 1);
    }
}

// ============================================================================
extern "C" void kernel_launch(void* const* d_in, const int* in_sizes, int n_in,
                              void* d_out, int out_size) {
    const float* x    = (const float*)d_in[0];
    const float* w_is = (const float*)d_in[1];
    const float* b_is = (const float*)d_in[2];
    const float* w_ss = (const float*)d_in[3];
    const float* b_ss = (const float*)d_in[4];
    float* out = (float*)d_out;

    cudaFuncSetAttribute(zprep_kernel, cudaFuncAttributeMaxDynamicSharedMemorySize, ZPREP_SMEM);
    cudaFuncSetAttribute(scan_kernel,  cudaFuncAttributeMaxDynamicSharedMemorySize, SCAN_SMEM);

    init_kernel<<<520, 256>>>();
    zprep_kernel<<<dim3(512, 4), 256, ZPREP_SMEM>>>(x, w_is, b_is);
    scan_kernel<<<128, 128, SCAN_SMEM>>>(w_ss, b_is, b_ss, out);
}